// round 11
// baseline (speedup 1.0000x reference)
#include <cuda_runtime.h>
#include <cstdint>

#define T_STEPS 2048
#define BATCH   64
#define IDIM    512
#define HDIM    512

#define N_GROUPS 16           // chains of 4 batch rows
#define BLKS_PER_GROUP 16     // column blocks per chain (32 H-cols each)
#define B_PER_GROUP 4
#define COLS_PER_BLK 32

typedef unsigned long long u64;

// ---------------- scratch -----------------------------------------------
__device__ float g_xf[(long)T_STEPS * BATCH * HDIM];
__device__ float g_xh[(long)T_STEPS * BATCH * HDIM];
__device__ float g_hbuf[BATCH * HDIM];
__device__ float g_gbuf[BATCH * HDIM];
// flags: chain c -> [c*64 .. c*64+15] = phase A slots, [c*64+32 ..+47] = phase B
__device__ unsigned int g_flags[N_GROUPS * 64];

// ---------------- packed f32x2 helpers -----------------------------------
__device__ __forceinline__ u64 pack2(float x, float y) {
    u64 r; asm("mov.b64 %0, {%1, %2};" : "=l"(r) : "f"(x), "f"(y)); return r;
}
__device__ __forceinline__ u64 ffma2(u64 a, u64 b, u64 c) {
    u64 d; asm("fma.rn.f32x2 %0, %1, %2, %3;" : "=l"(d) : "l"(a), "l"(b), "l"(c));
    return d;
}
__device__ __forceinline__ float2 unpack2(u64 a) {
    float2 r; asm("mov.b64 {%0, %1}, %2;" : "=f"(r.x), "=f"(r.y) : "l"(a)); return r;
}
__device__ __forceinline__ float4 ldcg4(const float4* p) {
    float4 v;
    asm volatile("ld.global.cg.v4.f32 {%0,%1,%2,%3}, [%4];"
                 : "=f"(v.x), "=f"(v.y), "=f"(v.z), "=f"(v.w) : "l"(p));
    return v;
}
__device__ __forceinline__ void st_release(unsigned int* p, unsigned int v) {
    asm volatile("st.release.gpu.global.u32 [%0], %1;" :: "l"(p), "r"(v) : "memory");
}
__device__ __forceinline__ unsigned int ld_acq(const unsigned int* p) {
    unsigned int v;
    asm volatile("ld.acquire.gpu.global.u32 %0, [%1];" : "=r"(v) : "l"(p) : "memory");
    return v;
}
__device__ __forceinline__ float sigmoid_f(float x) {
    return __fdividef(1.0f, 1.0f + __expf(-x));
}
__device__ __forceinline__ float tanh_ap(float x) {
    float y; asm("tanh.approx.f32 %0, %1;" : "=f"(y) : "f"(x)); return y;
}

// wait until all 16 per-block flags of a phase reach tgt.
// 32 lanes read 16 slots (x2 duplication, one 64B line); no atomics.
__device__ __forceinline__ void flag_wait(const unsigned int* slots,
                                          unsigned int tgt)
{
    const unsigned int* p = slots + (threadIdx.x & 15);
    unsigned int v = ld_acq(p);
    while (__any_sync(0xFFFFFFFFu, v < tgt))
        v = ld_acq(p);
    __syncwarp();   // fence: propagate acquired visibility warp-wide
}

// ============================================================================
// Phase 1: input projections. Block (0,0,0) zeroes flags; blocks (x<16,0,0)
// seed g_hbuf from h0. Re-done every launch (graph-replay safe).
// ============================================================================
__global__ __launch_bounds__(256) void proj_kernel(
    const float* __restrict__ X,  const float* __restrict__ h0,
    const float* __restrict__ Wf, const float* __restrict__ bf,
    const float* __restrict__ Wh, const float* __restrict__ bh)
{
    if (blockIdx.y == 0 && blockIdx.z == 0) {
        if (blockIdx.x == 0) {
            #pragma unroll
            for (int q = 0; q < (N_GROUPS * 64) / 256; q++)
                g_flags[threadIdx.x + q * 256] = 0u;
        }
        if (blockIdx.x < 16) {
            const float4* s = (const float4*)&h0[blockIdx.x * 4 * HDIM];
            float4* d = (float4*)&g_hbuf[blockIdx.x * 4 * HDIM];
            d[threadIdx.x]       = s[threadIdx.x];
            d[threadIdx.x + 256] = s[threadIdx.x + 256];
        }
    }

    const float* W  = blockIdx.z ? Wh : Wf;
    const float* bv = blockIdx.z ? bh : bf;
    float* out = blockIdx.z ? g_xh : g_xf;

    __shared__ float As[16][132];
    __shared__ float Bs[16][68];

    const int tid = threadIdx.x;
    const int tx = tid & 15;
    const int ty = tid >> 4;
    const long m0 = (long)blockIdx.x * 128;
    const int  n0 = blockIdx.y * 64;

    u64 acc[4][4];
    #pragma unroll
    for (int p = 0; p < 4; p++)
        #pragma unroll
        for (int c = 0; c < 4; c++) acc[p][c] = 0ull;

    for (int k0 = 0; k0 < IDIM; k0 += 16) {
        #pragma unroll
        for (int q0 = 0; q0 < 2; q0++) {
            int q = tid + q0 * 256;
            int row = q >> 2;
            int kc  = (q & 3) * 4;
            float4 v = *(const float4*)&X[(m0 + row) * IDIM + k0 + kc];
            As[kc+0][row] = v.x; As[kc+1][row] = v.y;
            As[kc+2][row] = v.z; As[kc+3][row] = v.w;
        }
        {
            int row = tid >> 2;
            int kc  = (tid & 3) * 4;
            float4 v = *(const float4*)&W[(n0 + row) * IDIM + k0 + kc];
            Bs[kc+0][row] = v.x; Bs[kc+1][row] = v.y;
            Bs[kc+2][row] = v.z; Bs[kc+3][row] = v.w;
        }
        __syncthreads();

        #pragma unroll
        for (int kk = 0; kk < 16; kk++) {
            float4 a0 = *(const float4*)&As[kk][ty * 8];
            float4 a1 = *(const float4*)&As[kk][ty * 8 + 4];
            float4 b4 = *(const float4*)&Bs[kk][tx * 4];
            u64 a2[4] = { pack2(a0.x, a0.y), pack2(a0.z, a0.w),
                          pack2(a1.x, a1.y), pack2(a1.z, a1.w) };
            u64 bb[4] = { pack2(b4.x, b4.x), pack2(b4.y, b4.y),
                          pack2(b4.z, b4.z), pack2(b4.w, b4.w) };
            #pragma unroll
            for (int p = 0; p < 4; p++)
                #pragma unroll
                for (int c = 0; c < 4; c++)
                    acc[p][c] = ffma2(a2[p], bb[c], acc[p][c]);
        }
        __syncthreads();
    }

    float4 bias4 = *(const float4*)&bv[n0 + tx * 4];
    #pragma unroll
    for (int p = 0; p < 4; p++) {
        float2 c0 = unpack2(acc[p][0]);
        float2 c1 = unpack2(acc[p][1]);
        float2 c2 = unpack2(acc[p][2]);
        float2 c3 = unpack2(acc[p][3]);
        long mlo = m0 + ty * 8 + 2 * p;
        float4 lo = make_float4(c0.x + bias4.x, c1.x + bias4.y,
                                c2.x + bias4.z, c3.x + bias4.w);
        float4 hi = make_float4(c0.y + bias4.x, c1.y + bias4.y,
                                c2.y + bias4.z, c3.y + bias4.w);
        *(float4*)&out[mlo * HDIM + n0 + tx * 4]       = lo;
        *(float4*)&out[(mlo + 1) * HDIM + n0 + tx * 4] = hi;
    }
}

// ============================================================================
// Phase 2: persistent scan (R7 data path; atomic-free flag sync).
// 256 blocks x 128 threads, 2/SM. Chain = 4 batch rows x 16 column blocks.
// Warp w owns k-slice [w*128,+128) + finalize row w. Wf register-resident;
// Wh in conflict-free SMEM slices. Release = block bar + 1 st.release per
// block; wait = parallel acquire-poll of 16 flag slots. No atomics.
// ============================================================================
#define WH_STRIDE 132
#define SCAN_SMEM ((128 * WH_STRIDE + 4 * 512 + 512 + 512) * 4)

__global__ void __launch_bounds__(128, 2) scan_kernel(
    const float* __restrict__ h0,
    const float* __restrict__ Whf,
    const float* __restrict__ Whh,
    float* __restrict__ out)
{
    extern __shared__ float smem[];
    float* whs   = smem;                     // 128 slices x 132
    float* srcs  = whs + 128 * WH_STRIDE;    // 4 warps x 512 (warp-private)
    float* partA = srcs + 4 * 512;           // [row][ks][j] 4*4*32
    float* partB = partA + 512;

    const int tid = threadIdx.x;
    const int j   = tid & 31;      // lane = column within block
    const int w   = tid >> 5;      // warp = k-slice index AND finalize row
    const int grp = blockIdx.x >> 4;
    const int blk = blockIdx.x & 15;
    const int j0  = blk * COLS_PER_BLK;
    const int b0  = grp * B_PER_GROUP;
    const int kb  = w * 128;

    unsigned int* flagA = &g_flags[grp * 64];
    unsigned int* flagB = &g_flags[grp * 64 + 32];

    // Wf slice -> registers (128 floats = 64 u64)
    u64 wf2[64];
    #pragma unroll
    for (int i = 0; i < 32; i++) {
        float4 v = *(const float4*)&Whf[(j0 + j) * HDIM + kb + 4 * i];
        wf2[2*i] = pack2(v.x, v.y); wf2[2*i+1] = pack2(v.z, v.w);
    }
    // Wh slice -> private SMEM region (thread-local)
    float* wr = &whs[(w * 32 + j) * WH_STRIDE];
    #pragma unroll
    for (int i = 0; i < 32; i++)
        *(float4*)&wr[4 * i] = *(const float4*)&Whh[(j0 + j) * HDIM + kb + 4 * i];

    float hp = h0[(b0 + w) * HDIM + j0 + j];
    __syncthreads();

    float* sb = &srcs[w * 512];
    const long xstep = (long)BATCH * HDIM;
    long xoff = (long)(b0 + w) * HDIM + j0 + j;   // rolling [t,b,col] offset

    float f_reg = 0.0f;

    for (int t = 0; t < T_STEPS; t++) {
        const unsigned int tcur = (unsigned int)(t + 1);
        const float xf_v = __ldcs(&g_xf[xoff]);
        const float xh_v = __ldcs(&g_xh[xoff]);

        // ---- wait for h_{t-1} (all 16 blocks' flagB == t) ----
        if (t > 0) flag_wait(flagB, tcur - 1u);

        // ---- per-warp gather: 4 rows x own k-slice of h ----
        {
            const float4* hb = (const float4*)&g_hbuf[b0 * HDIM + kb];
            float4 v0 = ldcg4(hb + j);
            float4 v1 = ldcg4(hb + 128 + j);
            float4 v2 = ldcg4(hb + 256 + j);
            float4 v3 = ldcg4(hb + 384 + j);
            *(float4*)&sb[        4 * j] = v0;
            *(float4*)&sb[128 +   4 * j] = v1;
            *(float4*)&sb[256 +   4 * j] = v2;
            *(float4*)&sb[384 +   4 * j] = v3;
        }
        __syncwarp();

        // ---- GEMM A (f gate), Wf from registers ----
        {
            u64 a0 = 0ull, a1 = 0ull, a2 = 0ull, a3 = 0ull;
            #pragma unroll
            for (int i = 0; i < 32; i++) {
                u64 wlo = wf2[2*i], whi = wf2[2*i+1];
                float4 x0 = *(const float4*)&sb[        4 * i];
                float4 x1 = *(const float4*)&sb[128 +   4 * i];
                float4 x2 = *(const float4*)&sb[256 +   4 * i];
                float4 x3 = *(const float4*)&sb[384 +   4 * i];
                a0 = ffma2(wlo, pack2(x0.x, x0.y), a0);
                a0 = ffma2(whi, pack2(x0.z, x0.w), a0);
                a1 = ffma2(wlo, pack2(x1.x, x1.y), a1);
                a1 = ffma2(whi, pack2(x1.z, x1.w), a1);
                a2 = ffma2(wlo, pack2(x2.x, x2.y), a2);
                a2 = ffma2(whi, pack2(x2.z, x2.w), a2);
                a3 = ffma2(wlo, pack2(x3.x, x3.y), a3);
                a3 = ffma2(whi, pack2(x3.z, x3.w), a3);
            }
            float2 r0 = unpack2(a0), r1 = unpack2(a1);
            float2 r2 = unpack2(a2), r3 = unpack2(a3);
            partA[(0 * 4 + w) * 32 + j] = r0.x + r0.y;
            partA[(1 * 4 + w) * 32 + j] = r1.x + r1.y;
            partA[(2 * 4 + w) * 32 + j] = r2.x + r2.y;
            partA[(3 * 4 + w) * 32 + j] = r3.x + r3.y;
        }
        __syncthreads();

        // ---- finalize A: warp w owns row w; publish g ----
        {
            float s = xf_v;
            #pragma unroll
            for (int q = 0; q < 4; q++) s += partA[(w * 4 + q) * 32 + j];
            f_reg = sigmoid_f(s);
            g_gbuf[(b0 + w) * HDIM + j0 + j] = f_reg * hp;
        }
        __syncthreads();                       // all g stores of the block done
        if (tid == 0) st_release(&flagA[blk], tcur);   // ONE release per block

        // ---- wait for g_t ----
        flag_wait(flagA, tcur);

        // ---- per-warp gather of g ----
        {
            const float4* gb = (const float4*)&g_gbuf[b0 * HDIM + kb];
            float4 v0 = ldcg4(gb + j);
            float4 v1 = ldcg4(gb + 128 + j);
            float4 v2 = ldcg4(gb + 256 + j);
            float4 v3 = ldcg4(gb + 384 + j);
            *(float4*)&sb[        4 * j] = v0;
            *(float4*)&sb[128 +   4 * j] = v1;
            *(float4*)&sb[256 +   4 * j] = v2;
            *(float4*)&sb[384 +   4 * j] = v3;
        }
        __syncwarp();

        // ---- GEMM B (candidate), Wh from SMEM ----
        {
            u64 a0 = 0ull, a1 = 0ull, a2 = 0ull, a3 = 0ull;
            #pragma unroll
            for (int i = 0; i < 32; i++) {
                float4 wv = *(const float4*)&wr[4 * i];
                u64 wlo = pack2(wv.x, wv.y), whi = pack2(wv.z, wv.w);
                float4 x0 = *(const float4*)&sb[        4 * i];
                float4 x1 = *(const float4*)&sb[128 +   4 * i];
                float4 x2 = *(const float4*)&sb[256 +   4 * i];
                float4 x3 = *(const float4*)&sb[384 +   4 * i];
                a0 = ffma2(wlo, pack2(x0.x, x0.y), a0);
                a0 = ffma2(whi, pack2(x0.z, x0.w), a0);
                a1 = ffma2(wlo, pack2(x1.x, x1.y), a1);
                a1 = ffma2(whi, pack2(x1.z, x1.w), a1);
                a2 = ffma2(wlo, pack2(x2.x, x2.y), a2);
                a2 = ffma2(whi, pack2(x2.z, x2.w), a2);
                a3 = ffma2(wlo, pack2(x3.x, x3.y), a3);
                a3 = ffma2(whi, pack2(x3.z, x3.w), a3);
            }
            float2 r0 = unpack2(a0), r1 = unpack2(a1);
            float2 r2 = unpack2(a2), r3 = unpack2(a3);
            partB[(0 * 4 + w) * 32 + j] = r0.x + r0.y;
            partB[(1 * 4 + w) * 32 + j] = r1.x + r1.y;
            partB[(2 * 4 + w) * 32 + j] = r2.x + r2.y;
            partB[(3 * 4 + w) * 32 + j] = r3.x + r3.y;
        }
        __syncthreads();

        // ---- finalize B: blend, emit y and h ----
        {
            float s = xh_v;
            #pragma unroll
            for (int q = 0; q < 4; q++) s += partB[(w * 4 + q) * 32 + j];
            float ht = tanh_ap(s);
            float hn = fmaf(f_reg, ht - hp, hp);        // (1-f)h + f*ht
            __stcs(&out[xoff], hn);
            g_hbuf[(b0 + w) * HDIM + j0 + j] = hn;
            if (t == T_STEPS - 1)
                out[(long)T_STEPS * xstep + (b0 + w) * HDIM + j0 + j] = hn;
            hp = hn;
        }
        __syncthreads();                       // all h stores of the block done
        if (tid == 0) st_release(&flagB[blk], tcur);

        xoff += xstep;
    }
}

// ============================================================================
extern "C" void kernel_launch(void* const* d_in, const int* in_sizes, int n_in,
                              void* d_out, int out_size)
{
    const float* x   = (const float*)d_in[0];
    const float* h0  = (const float*)d_in[1];
    const float* Wxf = (const float*)d_in[2];
    const float* Whf = (const float*)d_in[3];
    const float* bf  = (const float*)d_in[4];
    const float* Wxh = (const float*)d_in[5];
    const float* Whh = (const float*)d_in[6];
    const float* bh  = (const float*)d_in[7];
    float* out = (float*)d_out;

    cudaFuncSetAttribute(scan_kernel,
                         cudaFuncAttributeMaxDynamicSharedMemorySize, SCAN_SMEM);

    dim3 pgrid((T_STEPS * BATCH) / 128, HDIM / 64, 2);
    proj_kernel<<<pgrid, 256>>>(x, h0, Wxf, bf, Wxh, bh);

    scan_kernel<<<N_GROUPS * BLKS_PER_GROUP, 128, SCAN_SMEM>>>(h0, Whf, Whh, out);
}